// round 7
// baseline (speedup 1.0000x reference)
#include <cuda_runtime.h>
#include <cuda_bf16.h>

// AdditiveDTMGP: 3-stage additive deep GP, Laplace kernel on dyadic design
// u_i = i/64 (i=1..63), whitened by Rinv (upper-triangular), reparam weights.
//
// Exact split: exp(-|x-u|) = e^{-x}e^{u} (u<=x) / e^{x}e^{-u} (u>x) collapses
// each 63-term sum to a 2-term table lookup at j = floor(64x). Stage 1 tables
// premultiplied by e^{-+j/64}, stored (P,Q) fp32; contribution =
// P*cosh t + Q*sinh t, t in [0,1/64) -> 2-term poly, no MUFU.
// Stages 2/3 exact (A,B) + exp. All tables fp32 (fp16 failed accuracy).
//
// fwd: half-warp per sample, lane = output channel; nonlinearities computed
// once per value and broadcast via SMEM float4; gather loops chunked (8 deep)
// into register arrays for MLP, dual accumulators for ILP.

#define MM 63

__device__ float2 g_T1[32 * 64 * 16];   // stage1 [f][j][o] : (P, Q)
__device__ float2 g_T2[16 * 64 * 16];   // stage2 [f][j][o] : (A, B)
__device__ float2 g_T3[64 * 16];        // stage3 [j][f]    : (A, B)
__device__ float  g_bsum1[16];
__device__ float  g_bsum2[16];
__device__ float  g_bsum3;
__device__ float  g_klpart[65];

__device__ __forceinline__ float kl_term(float mu, float s) {
    return fmaf(0.5f, fmaf(s, s, mu * mu), -__logf(s)) - 0.5f;
}

// ---------------------------------------------------------------------------
// Prep: 65 blocks. blocks 0..63 = one feature-column table + weight-KL part,
// block 64 = bias sums + bias-KL. Fully thread-parallel.
// ---------------------------------------------------------------------------
__global__ void __launch_bounds__(256) build_tables(
    const float* __restrict__ U, const float* __restrict__ Rinv,
    const float* __restrict__ mw1, const float* __restrict__ rw1, const float* __restrict__ ew1,
    const float* __restrict__ mw2, const float* __restrict__ rw2, const float* __restrict__ ew2,
    const float* __restrict__ mw3, const float* __restrict__ rw3, const float* __restrict__ ew3,
    const float* __restrict__ mb1, const float* __restrict__ rb1, const float* __restrict__ eb1,
    const float* __restrict__ mb2, const float* __restrict__ rb2, const float* __restrict__ eb2,
    const float* __restrict__ mb3, const float* __restrict__ rb3, const float* __restrict__ eb3)
{
    const int blk = blockIdx.x, t = threadIdx.x;
    __shared__ float red[256];

    if (blk == 64) {
        float kl = 0.f;
        for (int i = t; i < 32 * 16; i += 256) kl += kl_term(mb1[i], log1pf(__expf(rb1[i])));
        for (int i = t; i < 16 * 16; i += 256) kl += kl_term(mb2[i], log1pf(__expf(rb2[i])));
        for (int i = t; i < 16;      i += 256) kl += kl_term(mb3[i], log1pf(__expf(rb3[i])));
        if (t < 16) {
            float s = 0.f;
            for (int f = 0; f < 32; f++) {
                int i = f * 16 + t;
                s += mb1[i] + log1pf(__expf(rb1[i])) * eb1[i];
            }
            g_bsum1[t] = s;
        } else if (t < 32) {
            int o = t - 16;
            float s = 0.f;
            for (int f = 0; f < 16; f++) {
                int i = f * 16 + o;
                s += mb2[i] + log1pf(__expf(rb2[i])) * eb2[i];
            }
            g_bsum2[o] = s;
        } else if (t == 32) {
            float s = 0.f;
            for (int f = 0; f < 16; f++)
                s += mb3[f] + log1pf(__expf(rb3[f])) * eb3[f];
            g_bsum3 = s;
        }
        red[t] = kl;
        __syncthreads();
        for (int s = 128; s > 0; s >>= 1) {
            if (t < s) red[t] += red[t + s];
            __syncthreads();
        }
        if (t == 0) g_klpart[64] = red[0];
        return;
    }

    __shared__ float sR[64 * MM];   // padded: row m=63 scratch
    __shared__ float sW[16 * MM];
    __shared__ float sP[16 * 64];   // P[o][i] = e^{i/64} V[o][i-1], i=1..63
    __shared__ float sQ[16 * 64];
    __shared__ float sEJ[64], sEMJ[64];

    int stage, f, O;
    const float *mw, *rw, *ew;
    if (blk < 32)      { stage = 1; f = blk;      O = 16; mw = mw1; rw = rw1; ew = ew1; }
    else if (blk < 48) { stage = 2; f = blk - 32; O = 16; mw = mw2; rw = rw2; ew = ew2; }
    else               { stage = 3; f = blk - 48; O = 1;  mw = mw3; rw = rw3; ew = ew3; }

    #pragma unroll 4
    for (int i = t; i < MM * MM; i += 256) sR[i] = Rinv[i];
    if (t < 64) { float v = (float)t * 0.015625f; sEJ[t] = __expf(v); sEMJ[t] = __expf(-v); }

    float kl = 0.f;
    for (int i = t; i < O * MM; i += 256) {
        float mu = mw[(f * O) * MM + i];
        float s  = log1pf(__expf(rw[(f * O) * MM + i]));
        sW[i] = mu + s * ew[(f * O) * MM + i];
        kl += kl_term(mu, s);
    }
    red[t] = kl;
    __syncthreads();

    // Phase B: 4 consecutive m of one o per thread.
    {
        int e4 = t * 4;
        if (e4 < O * 64) {
            int o = e4 >> 6, m0 = e4 & 63;
            const float* w = &sW[o * MM];
            const float* r0 = &sR[(m0 + 0) * MM];
            const float* r1 = &sR[(m0 + 1) * MM];
            const float* r2 = &sR[(m0 + 2) * MM];
            const float* r3 = &sR[(m0 + 3) * MM];
            float v0 = 0.f, v1 = 0.f, v2 = 0.f, v3 = 0.f;
            #pragma unroll
            for (int n = 0; n < MM; n++) {
                float wn = w[n];
                v0 = fmaf(r0[n], wn, v0);
                v1 = fmaf(r1[n], wn, v1);
                v2 = fmaf(r2[n], wn, v2);
                v3 = fmaf(r3[n], wn, v3);
            }
            float vv[4] = {v0, v1, v2, v3};
            #pragma unroll
            for (int k = 0; k < 4; k++) {
                int m = m0 + k;
                if (m < MM) {
                    sP[o * 64 + (m + 1)] = vv[k] * sEJ[m + 1];
                    sQ[o * 64 + (m + 1)] = vv[k] * sEMJ[m + 1];
                }
            }
        }
        if (t < O) { sP[t * 64] = 0.f; sQ[t * 64] = 0.f; }
    }
    __syncthreads();

    for (int s = 128; s > 0; s >>= 1) {
        if (t < s) red[t] += red[t + s];
        __syncthreads();
    }
    if (t == 0) g_klpart[blk] = red[0];

    // Phase C: A = sum_{i<=j} P[i], B = sum_{i>j} Q[i].
    for (int e = t; e < O * 64; e += 256) {
        int o = e >> 6, j = e & 63;
        const float* p = &sP[o * 64];
        const float* q = &sQ[o * 64];
        float A = 0.f, B = 0.f;
        #pragma unroll
        for (int i = 1; i <= 63; i++) {
            A += (i <= j) ? p[i] : 0.f;
            B += (i >  j) ? q[i] : 0.f;
        }
        if (stage == 1) {
            float At = A * sEMJ[j];
            float Bt = B * sEJ[j];
            g_T1[(f * 64 + j) * 16 + o] = make_float2(At + Bt, Bt - At);
        } else if (stage == 2) {
            g_T2[(f * 64 + j) * 16 + o] = make_float2(A, B);
        } else {
            g_T3[j * 16 + f] = make_float2(A, B);
        }
    }
}

// ---------------------------------------------------------------------------
// Forward.
// ---------------------------------------------------------------------------
__global__ void __launch_bounds__(256) fwd_kernel(
    const float* __restrict__ x, float* __restrict__ out, int nB, int klIdx)
{
    __shared__ float4 sT[8][64];   // [warp][sub*32 + f]

    // KL: warp-parallel deterministic tree sum of the 65 partials.
    if (blockIdx.x == 0 && threadIdx.x < 32) {
        int l = threadIdx.x;
        float s = g_klpart[l] + g_klpart[l + 32];
        if (l == 0) s += g_klpart[64];
        #pragma unroll
        for (int d = 16; d > 0; d >>= 1)
            s += __shfl_xor_sync(0xFFFFFFFFu, s, d);
        if (l == 0) out[klIdx] = s;
    }

    const int warp = threadIdx.x >> 5, lane = threadIdx.x & 31;
    const int sub = lane >> 4, o = lane & 15;
    const int b = blockIdx.x * 16 + warp * 2 + sub;
    const int bc = (b < nB) ? b : (nB - 1);
    const unsigned mask = 0xFFFFu << (sub << 4);

    float4* tw = &sT[warp][sub * 32];

    const float xv0 = __ldg(&x[bc * 32 + o]);
    const float xv1 = __ldg(&x[bc * 32 + 16 + o]);
    const float bs1 = __ldg(&g_bsum1[o]);
    const float bs2 = __ldg(&g_bsum2[o]);
    const float bs3 = __ldg(&g_bsum3);

    // ---- stage 1 precompute: own (cosh t, sinh t, j*128) for xv0, xv1 ----
    {
        float j0f = fminf(fmaxf(xv0 * 64.f, 0.f), 63.f);
        int   j0  = (int)j0f;
        float t0  = fmaf((float)j0, -0.015625f, xv0);
        float t02 = t0 * t0;
        tw[o] = make_float4(fmaf(t02, 0.5f, 1.f),
                            t0 * fmaf(t02, 0.16666667f, 1.f),
                            __int_as_float(j0 * 128), 0.f);
        float j1f = fminf(fmaxf(xv1 * 64.f, 0.f), 63.f);
        int   j1  = (int)j1f;
        float t1  = fmaf((float)j1, -0.015625f, xv1);
        float t12 = t1 * t1;
        tw[16 + o] = make_float4(fmaf(t12, 0.5f, 1.f),
                                 t1 * fmaf(t12, 0.16666667f, 1.f),
                                 __int_as_float(j1 * 128), 0.f);
    }
    __syncwarp();

    // ---- stage 1 loop: 4 chunks of 8, batched loads, dual accumulators ----
    const char* base1 = (const char*)g_T1 + o * 8;
    float acc0 = 0.f, acc1 = 0.f;
    #pragma unroll
    for (int c = 0; c < 4; c++) {
        float4 tr[8];
        float2 pq[8];
        #pragma unroll
        for (int k = 0; k < 8; k++) tr[k] = tw[c * 8 + k];
        #pragma unroll
        for (int k = 0; k < 8; k++)
            pq[k] = *(const float2*)(base1 + (c * 8 + k) * 8192 + __float_as_int(tr[k].z));
        #pragma unroll
        for (int k = 0; k < 8; k += 2) {
            acc0 = fmaf(pq[k].x,     tr[k].x,     fmaf(pq[k].y,     tr[k].y,     acc0));
            acc1 = fmaf(pq[k + 1].x, tr[k + 1].x, fmaf(pq[k + 1].y, tr[k + 1].y, acc1));
        }
    }
    float h1 = (acc0 + acc1) + bs1;
    __syncwarp();

    // ---- stage 2 precompute: own (e^{-h}, e^{h}, j*128) ----
    {
        float ex  = __expf(h1);
        float emx = __expf(-h1);
        int j = (int)fminf(fmaxf(h1 * 64.f, 0.f), 63.f);
        tw[o] = make_float4(emx, ex, __int_as_float(j * 128), 0.f);
    }
    __syncwarp();

    // ---- stage 2 loop: 2 chunks of 8 ----
    const char* base2 = (const char*)g_T2 + o * 8;
    acc0 = 0.f; acc1 = 0.f;
    #pragma unroll
    for (int c = 0; c < 2; c++) {
        float4 tr[8];
        float2 ab[8];
        #pragma unroll
        for (int k = 0; k < 8; k++) tr[k] = tw[c * 8 + k];
        #pragma unroll
        for (int k = 0; k < 8; k++)
            ab[k] = *(const float2*)(base2 + (c * 8 + k) * 8192 + __float_as_int(tr[k].z));
        #pragma unroll
        for (int k = 0; k < 8; k += 2) {
            acc0 = fmaf(tr[k].x,     ab[k].x,     fmaf(tr[k].y,     ab[k].y,     acc0));
            acc1 = fmaf(tr[k + 1].x, ab[k + 1].x, fmaf(tr[k + 1].y, ab[k + 1].y, acc1));
        }
    }
    float h2 = (acc0 + acc1) + bs2;

    // ---- stage 3: 16 -> 1 (lane o is feature o) ----
    {
        float ex  = __expf(h2);
        float emx = __expf(-h2);
        int j = (int)fminf(fmaxf(h2 * 64.f, 0.f), 63.f);
        float2 tv = __ldg(&g_T3[j * 16 + o]);
        float c = fmaf(emx, tv.x, ex * tv.y);
        c += __shfl_xor_sync(mask, c, 8);
        c += __shfl_xor_sync(mask, c, 4);
        c += __shfl_xor_sync(mask, c, 2);
        c += __shfl_xor_sync(mask, c, 1);
        if (o == 0 && b < nB) out[b] = c + bs3;
    }
}

// ---------------------------------------------------------------------------
extern "C" void kernel_launch(void* const* d_in, const int* in_sizes, int n_in,
                              void* d_out, int out_size)
{
    const float* x    = (const float*)d_in[0];
    const float* U    = (const float*)d_in[1];
    const float* Rinv = (const float*)d_in[2];

    const float* mw1 = (const float*)d_in[3];
    const float* rw1 = (const float*)d_in[4];
    const float* mb1 = (const float*)d_in[5];
    const float* rb1 = (const float*)d_in[6];
    const float* ew1 = (const float*)d_in[7];
    const float* eb1 = (const float*)d_in[8];

    const float* mw2 = (const float*)d_in[9];
    const float* rw2 = (const float*)d_in[10];
    const float* mb2 = (const float*)d_in[11];
    const float* rb2 = (const float*)d_in[12];
    const float* ew2 = (const float*)d_in[13];
    const float* eb2 = (const float*)d_in[14];

    const float* mw3 = (const float*)d_in[15];
    const float* rw3 = (const float*)d_in[16];
    const float* mb3 = (const float*)d_in[17];
    const float* rb3 = (const float*)d_in[18];
    const float* ew3 = (const float*)d_in[19];
    const float* eb3 = (const float*)d_in[20];

    const int nB = in_sizes[0] / 32;
    float* out = (float*)d_out;

    build_tables<<<65, 256>>>(U, Rinv,
                              mw1, rw1, ew1, mw2, rw2, ew2, mw3, rw3, ew3,
                              mb1, rb1, eb1, mb2, rb2, eb2, mb3, rb3, eb3);
    fwd_kernel<<<(nB + 15) / 16, 256>>>(x, out, nB, out_size - 1);
}

// round 8
// speedup vs baseline: 1.2028x; 1.2028x over previous
#include <cuda_runtime.h>
#include <cuda_bf16.h>

// AdditiveDTMGP: 3-stage additive deep GP, Laplace kernel on dyadic design
// u_i = i/64 (i=1..63), whitened by Rinv (upper-triangular), reparam weights.
//
// Exact split: exp(-|x-u|) = e^{-x}e^{u} (u<=x) / e^{x}e^{-u} (u>x) collapses
// each 63-term sum to a 2-term table lookup at j = floor(64x). Stage 1 tables
// premultiplied by e^{-+j/64}, stored (P,Q) fp32: contribution =
// P*cosh t + Q*sinh t, t in [0,1/64) -> 2-term poly, no MUFU. Stages 2/3
// exact (A,B) + exp. All tables fp32 (fp16 failed accuracy at 5e-3).
//
// build: 209 blocks — stages 1/2 split 4-ways by output channel (4 o's per
// block) so the whole chip is busy and per-thread chains are ~63 FMA.
// fwd: half-warp per sample, lane = output channel, nonlinearities computed
// once and broadcast via SMEM float4 (R5 form: 32 regs, 8 blocks/SM, TLP).

#define MM 63
#define NBLK 209   // 128 stage1 + 64 stage2 + 16 stage3 + 1 bias

__device__ float2 g_T1[32 * 64 * 16];   // stage1 [f][j][o] : (P, Q)
__device__ float2 g_T2[16 * 64 * 16];   // stage2 [f][j][o] : (A, B)
__device__ float2 g_T3[64 * 16];        // stage3 [j][f]    : (A, B)
__device__ float  g_bsum1[16];
__device__ float  g_bsum2[16];
__device__ float  g_bsum3;
__device__ float  g_klpart[NBLK];

__device__ __forceinline__ float kl_term(float mu, float s) {
    return fmaf(0.5f, fmaf(s, s, mu * mu), -__logf(s)) - 0.5f;
}

// ---------------------------------------------------------------------------
// Prep: 209 blocks.
//   [0,128)   stage1: f = blk>>2, o-range [(blk&3)*4, +4)
//   [128,192) stage2: f = (blk-128)>>2, o-range [(blk&3)*4, +4)
//   [192,208) stage3: f = blk-192, O=1
//   208       bias sums + bias-KL
// ---------------------------------------------------------------------------
__global__ void __launch_bounds__(256) build_tables(
    const float* __restrict__ U, const float* __restrict__ Rinv,
    const float* __restrict__ mw1, const float* __restrict__ rw1, const float* __restrict__ ew1,
    const float* __restrict__ mw2, const float* __restrict__ rw2, const float* __restrict__ ew2,
    const float* __restrict__ mw3, const float* __restrict__ rw3, const float* __restrict__ ew3,
    const float* __restrict__ mb1, const float* __restrict__ rb1, const float* __restrict__ eb1,
    const float* __restrict__ mb2, const float* __restrict__ rb2, const float* __restrict__ eb2,
    const float* __restrict__ mb3, const float* __restrict__ rb3, const float* __restrict__ eb3)
{
    const int blk = blockIdx.x, t = threadIdx.x;
    __shared__ float red[256];

    if (blk == 208) {
        float kl = 0.f;
        for (int i = t; i < 32 * 16; i += 256) kl += kl_term(mb1[i], log1pf(__expf(rb1[i])));
        for (int i = t; i < 16 * 16; i += 256) kl += kl_term(mb2[i], log1pf(__expf(rb2[i])));
        for (int i = t; i < 16;      i += 256) kl += kl_term(mb3[i], log1pf(__expf(rb3[i])));
        if (t < 16) {
            float s = 0.f;
            for (int f = 0; f < 32; f++) {
                int i = f * 16 + t;
                s += mb1[i] + log1pf(__expf(rb1[i])) * eb1[i];
            }
            g_bsum1[t] = s;
        } else if (t < 32) {
            int o = t - 16;
            float s = 0.f;
            for (int f = 0; f < 16; f++) {
                int i = f * 16 + o;
                s += mb2[i] + log1pf(__expf(rb2[i])) * eb2[i];
            }
            g_bsum2[o] = s;
        } else if (t == 32) {
            float s = 0.f;
            for (int f = 0; f < 16; f++)
                s += mb3[f] + log1pf(__expf(rb3[f])) * eb3[f];
            g_bsum3 = s;
        }
        red[t] = kl;
        __syncthreads();
        for (int s = 128; s > 0; s >>= 1) {
            if (t < s) red[t] += red[t + s];
            __syncthreads();
        }
        if (t == 0) g_klpart[208] = red[0];
        return;
    }

    __shared__ float sR[MM * MM];
    __shared__ float sW[4 * MM];
    __shared__ float sP[4 * 64];   // P[ol][i] = e^{i/64} V[ol][i-1], i=1..63
    __shared__ float sQ[4 * 64];
    __shared__ float sEU[MM], sEMU[MM];
    __shared__ float sEJ[64], sEMJ[64];

    int stage, f, oB, Ocnt, Otot;
    const float *mw, *rw, *ew;
    if (blk < 128) {
        stage = 1; f = blk >> 2; oB = (blk & 3) * 4; Ocnt = 4; Otot = 16;
        mw = mw1; rw = rw1; ew = ew1;
    } else if (blk < 192) {
        int bb = blk - 128;
        stage = 2; f = bb >> 2; oB = (bb & 3) * 4; Ocnt = 4; Otot = 16;
        mw = mw2; rw = rw2; ew = ew2;
    } else {
        stage = 3; f = blk - 192; oB = 0; Ocnt = 1; Otot = 1;
        mw = mw3; rw = rw3; ew = ew3;
    }

    #pragma unroll 4
    for (int i = t; i < MM * MM; i += 256) sR[i] = Rinv[i];
    if (t < MM) { float u = U[t]; sEU[t] = __expf(u); sEMU[t] = __expf(-u); }
    if (t < 64) { float v = (float)t * 0.015625f; sEJ[t] = __expf(v); sEMJ[t] = __expf(-v); }

    // Phase A: effective weights for this o-range + weight-KL partial
    float kl = 0.f;
    for (int i = t; i < Ocnt * MM; i += 256) {
        int ol = i / MM, n = i % MM;
        int gi = (f * Otot + oB + ol) * MM + n;
        float mu = mw[gi];
        float s  = log1pf(__expf(rw[gi]));
        sW[i] = mu + s * ew[gi];
        kl += kl_term(mu, s);
    }
    red[t] = kl;
    __syncthreads();

    // Phase B: one V entry per thread (63-FMA chain).
    // V[ol][m] = sum_n Rinv[m][n] * W[ol][n]; store P/Q at [ol][m+1].
    for (int i = t; i < Ocnt * MM; i += 256) {
        int ol = i / MM, m = i % MM;
        const float* r = &sR[m * MM];
        const float* w = &sW[ol * MM];
        float v = 0.f;
        #pragma unroll
        for (int n = 0; n < MM; n++) v = fmaf(r[n], w[n], v);
        sP[ol * 64 + (m + 1)] = v * sEU[m];
        sQ[ol * 64 + (m + 1)] = v * sEMU[m];
    }
    if (t < Ocnt) { sP[t * 64] = 0.f; sQ[t * 64] = 0.f; }
    __syncthreads();

    for (int s = 128; s > 0; s >>= 1) {
        if (t < s) red[t] += red[t + s];
        __syncthreads();
    }
    if (t == 0) g_klpart[blk] = red[0];

    // Phase C: one (ol,j) entry per thread.
    // A = sum_{i<=j} P[i], B = sum_{i>j} Q[i].
    for (int e = t; e < Ocnt * 64; e += 256) {
        int ol = e >> 6, j = e & 63;
        const float* p = &sP[ol * 64];
        const float* q = &sQ[ol * 64];
        float A = 0.f, B = 0.f;
        #pragma unroll
        for (int i = 1; i <= 63; i++) {
            A += (i <= j) ? p[i] : 0.f;
            B += (i >  j) ? q[i] : 0.f;
        }
        if (stage == 1) {
            float At = A * sEMJ[j];
            float Bt = B * sEJ[j];
            g_T1[(f * 64 + j) * 16 + (oB + ol)] = make_float2(At + Bt, Bt - At);
        } else if (stage == 2) {
            g_T2[(f * 64 + j) * 16 + (oB + ol)] = make_float2(A, B);
        } else {
            g_T3[j * 16 + f] = make_float2(A, B);
        }
    }
}

// ---------------------------------------------------------------------------
// Forward (R5 form: 32 regs, TLP-driven).
// ---------------------------------------------------------------------------
__global__ void __launch_bounds__(256) fwd_kernel(
    const float* __restrict__ x, float* __restrict__ out, int nB, int klIdx)
{
    __shared__ float4 sT[8][64];   // [warp][sub*32 + f]

    // KL: warp-parallel deterministic sum of the NBLK partials.
    if (blockIdx.x == 0 && threadIdx.x < 32) {
        int l = threadIdx.x;
        float s = 0.f;
        for (int i = l; i < NBLK; i += 32) s += g_klpart[i];
        #pragma unroll
        for (int d = 16; d > 0; d >>= 1)
            s += __shfl_xor_sync(0xFFFFFFFFu, s, d);
        if (l == 0) out[klIdx] = s;
    }

    const int warp = threadIdx.x >> 5, lane = threadIdx.x & 31;
    const int sub = lane >> 4, o = lane & 15;
    const int b = blockIdx.x * 16 + warp * 2 + sub;
    const int bc = (b < nB) ? b : (nB - 1);
    const unsigned mask = 0xFFFFu << (sub << 4);

    float4* tw = &sT[warp][sub * 32];

    const float xv0 = __ldg(&x[bc * 32 + o]);
    const float xv1 = __ldg(&x[bc * 32 + 16 + o]);
    const float bs1 = __ldg(&g_bsum1[o]);
    const float bs2 = __ldg(&g_bsum2[o]);
    const float bs3 = __ldg(&g_bsum3);

    // ---- stage 1 precompute: own (cosh t, sinh t, j*128) for xv0, xv1 ----
    {
        float j0f = fminf(fmaxf(xv0 * 64.f, 0.f), 63.f);
        int   j0  = (int)j0f;
        float t0  = fmaf((float)j0, -0.015625f, xv0);
        float t02 = t0 * t0;
        tw[o] = make_float4(fmaf(t02, 0.5f, 1.f),
                            t0 * fmaf(t02, 0.16666667f, 1.f),
                            __int_as_float(j0 * 128), 0.f);
        float j1f = fminf(fmaxf(xv1 * 64.f, 0.f), 63.f);
        int   j1  = (int)j1f;
        float t1  = fmaf((float)j1, -0.015625f, xv1);
        float t12 = t1 * t1;
        tw[16 + o] = make_float4(fmaf(t12, 0.5f, 1.f),
                                 t1 * fmaf(t12, 0.16666667f, 1.f),
                                 __int_as_float(j1 * 128), 0.f);
    }
    __syncwarp();

    const char* base1 = (const char*)g_T1 + o * 8;
    float acc = 0.f;
    #pragma unroll
    for (int f = 0; f < 32; f++) {
        float4 tr = tw[f];
        const float2 pq = *(const float2*)(base1 + f * 8192 + __float_as_int(tr.z));
        acc = fmaf(pq.x, tr.x, fmaf(pq.y, tr.y, acc));
    }
    float h1 = acc + bs1;
    __syncwarp();

    // ---- stage 2 precompute: own (e^{-h}, e^{h}, j*128) ----
    {
        float ex  = __expf(h1);
        float emx = __expf(-h1);
        int j = (int)fminf(fmaxf(h1 * 64.f, 0.f), 63.f);
        tw[o] = make_float4(emx, ex, __int_as_float(j * 128), 0.f);
    }
    __syncwarp();

    const char* base2 = (const char*)g_T2 + o * 8;
    acc = 0.f;
    #pragma unroll
    for (int f = 0; f < 16; f++) {
        float4 tr = tw[f];
        const float2 ab = *(const float2*)(base2 + f * 8192 + __float_as_int(tr.z));
        acc = fmaf(tr.x, ab.x, fmaf(tr.y, ab.y, acc));
    }
    float h2 = acc + bs2;

    // ---- stage 3: 16 -> 1 (lane o is feature o) ----
    {
        float ex  = __expf(h2);
        float emx = __expf(-h2);
        int j = (int)fminf(fmaxf(h2 * 64.f, 0.f), 63.f);
        float2 tv = __ldg(&g_T3[j * 16 + o]);
        float c = fmaf(emx, tv.x, ex * tv.y);
        c += __shfl_xor_sync(mask, c, 8);
        c += __shfl_xor_sync(mask, c, 4);
        c += __shfl_xor_sync(mask, c, 2);
        c += __shfl_xor_sync(mask, c, 1);
        if (o == 0 && b < nB) out[b] = c + bs3;
    }
}

// ---------------------------------------------------------------------------
extern "C" void kernel_launch(void* const* d_in, const int* in_sizes, int n_in,
                              void* d_out, int out_size)
{
    const float* x    = (const float*)d_in[0];
    const float* U    = (const float*)d_in[1];
    const float* Rinv = (const float*)d_in[2];

    const float* mw1 = (const float*)d_in[3];
    const float* rw1 = (const float*)d_in[4];
    const float* mb1 = (const float*)d_in[5];
    const float* rb1 = (const float*)d_in[6];
    const float* ew1 = (const float*)d_in[7];
    const float* eb1 = (const float*)d_in[8];

    const float* mw2 = (const float*)d_in[9];
    const float* rw2 = (const float*)d_in[10];
    const float* mb2 = (const float*)d_in[11];
    const float* rb2 = (const float*)d_in[12];
    const float* ew2 = (const float*)d_in[13];
    const float* eb2 = (const float*)d_in[14];

    const float* mw3 = (const float*)d_in[15];
    const float* rw3 = (const float*)d_in[16];
    const float* mb3 = (const float*)d_in[17];
    const float* rb3 = (const float*)d_in[18];
    const float* ew3 = (const float*)d_in[19];
    const float* eb3 = (const float*)d_in[20];

    const int nB = in_sizes[0] / 32;
    float* out = (float*)d_out;

    build_tables<<<NBLK, 256>>>(U, Rinv,
                                mw1, rw1, ew1, mw2, rw2, ew2, mw3, rw3, ew3,
                                mb1, rb1, eb1, mb2, rb2, eb2, mb3, rb3, eb3);
    fwd_kernel<<<(nB + 15) / 16, 256>>>(x, out, nB, out_size - 1);
}

// round 9
// speedup vs baseline: 1.2807x; 1.0648x over previous
#include <cuda_runtime.h>
#include <cuda_bf16.h>

// AdditiveDTMGP: 3-stage additive deep GP, Laplace kernel on dyadic design
// u_i = i/64 (i=1..63), whitened by Rinv (upper-triangular), reparam weights.
//
// Exact split: exp(-|x-u|) = e^{-x}e^{u} (u<=x) / e^{x}e^{-u} (u>x) collapses
// each 63-term sum to a 2-term table lookup at j = floor(64x). Stage 1 tables
// premultiplied by e^{-+j/64}, stored (P,Q) fp32: contribution =
// P*cosh t + Q*sinh t, t in [0,1/64). Stages 2/3 exact (A,B) + exp.
//
// build: 209 blocks (stages 1/2 split 4-ways by output channel).
// fwd: half-warp per sample, lane = output channel. Nonlinearities computed
// once per value, broadcast via per-warp SMEM float2 slots with the 6-bit
// bucket index j EMBEDDED in the low mantissa bits of the first component
// (<= 63-ulp perturbation, used multiplicatively -> ~7.5e-6 rel) so the
// inner loop is LDS.64 + extract + LDG.64 + 2 FMA.

#define MM 63
#define NBLK 209   // 128 stage1 + 64 stage2 + 16 stage3 + 1 bias

__device__ float2 g_T1[32 * 64 * 16];   // stage1 [f][j][o] : (P, Q)
__device__ float2 g_T2[16 * 64 * 16];   // stage2 [f][j][o] : (A, B)
__device__ float2 g_T3[64 * 16];        // stage3 [j][f]    : (A, B)
__device__ float  g_bsum1[16];
__device__ float  g_bsum2[16];
__device__ float  g_bsum3;
__device__ float  g_klpart[NBLK];

__device__ __forceinline__ float kl_term(float mu, float s) {
    return fmaf(0.5f, fmaf(s, s, mu * mu), -__logf(s)) - 0.5f;
}

// Embed 6-bit j into low mantissa bits of v (rounded): value error <= ~63 ulp.
__device__ __forceinline__ float embed_j(float v, int j) {
    unsigned b = (__float_as_uint(v) + 32u) & ~63u;
    return __uint_as_float(b | (unsigned)j);
}

// ---------------------------------------------------------------------------
// Prep: 209 blocks.
//   [0,128)   stage1: f = blk>>2, o-range [(blk&3)*4, +4)
//   [128,192) stage2: f = (blk-128)>>2, o-range [(blk&3)*4, +4)
//   [192,208) stage3: f = blk-192, O=1
//   208       bias sums + bias-KL
// ---------------------------------------------------------------------------
__global__ void __launch_bounds__(256) build_tables(
    const float* __restrict__ U, const float* __restrict__ Rinv,
    const float* __restrict__ mw1, const float* __restrict__ rw1, const float* __restrict__ ew1,
    const float* __restrict__ mw2, const float* __restrict__ rw2, const float* __restrict__ ew2,
    const float* __restrict__ mw3, const float* __restrict__ rw3, const float* __restrict__ ew3,
    const float* __restrict__ mb1, const float* __restrict__ rb1, const float* __restrict__ eb1,
    const float* __restrict__ mb2, const float* __restrict__ rb2, const float* __restrict__ eb2,
    const float* __restrict__ mb3, const float* __restrict__ rb3, const float* __restrict__ eb3)
{
    const int blk = blockIdx.x, t = threadIdx.x;
    __shared__ float red[256];

    if (blk == 208) {
        float kl = 0.f;
        for (int i = t; i < 32 * 16; i += 256) kl += kl_term(mb1[i], log1pf(__expf(rb1[i])));
        for (int i = t; i < 16 * 16; i += 256) kl += kl_term(mb2[i], log1pf(__expf(rb2[i])));
        for (int i = t; i < 16;      i += 256) kl += kl_term(mb3[i], log1pf(__expf(rb3[i])));
        if (t < 16) {
            float s = 0.f;
            for (int f = 0; f < 32; f++) {
                int i = f * 16 + t;
                s += mb1[i] + log1pf(__expf(rb1[i])) * eb1[i];
            }
            g_bsum1[t] = s;
        } else if (t < 32) {
            int o = t - 16;
            float s = 0.f;
            for (int f = 0; f < 16; f++) {
                int i = f * 16 + o;
                s += mb2[i] + log1pf(__expf(rb2[i])) * eb2[i];
            }
            g_bsum2[o] = s;
        } else if (t == 32) {
            float s = 0.f;
            for (int f = 0; f < 16; f++)
                s += mb3[f] + log1pf(__expf(rb3[f])) * eb3[f];
            g_bsum3 = s;
        }
        red[t] = kl;
        __syncthreads();
        for (int s = 128; s > 0; s >>= 1) {
            if (t < s) red[t] += red[t + s];
            __syncthreads();
        }
        if (t == 0) g_klpart[208] = red[0];
        return;
    }

    __shared__ float sR[MM * MM];
    __shared__ float sW[4 * MM];
    __shared__ float sP[4 * 64];   // P[ol][i] = e^{i/64} V[ol][i-1], i=1..63
    __shared__ float sQ[4 * 64];
    __shared__ float sEU[MM], sEMU[MM];
    __shared__ float sEJ[64], sEMJ[64];

    int stage, f, oB, Ocnt, Otot;
    const float *mw, *rw, *ew;
    if (blk < 128) {
        stage = 1; f = blk >> 2; oB = (blk & 3) * 4; Ocnt = 4; Otot = 16;
        mw = mw1; rw = rw1; ew = ew1;
    } else if (blk < 192) {
        int bb = blk - 128;
        stage = 2; f = bb >> 2; oB = (bb & 3) * 4; Ocnt = 4; Otot = 16;
        mw = mw2; rw = rw2; ew = ew2;
    } else {
        stage = 3; f = blk - 192; oB = 0; Ocnt = 1; Otot = 1;
        mw = mw3; rw = rw3; ew = ew3;
    }

    #pragma unroll 4
    for (int i = t; i < MM * MM; i += 256) sR[i] = Rinv[i];
    if (t < MM) { float u = U[t]; sEU[t] = __expf(u); sEMU[t] = __expf(-u); }
    if (t < 64) { float v = (float)t * 0.015625f; sEJ[t] = __expf(v); sEMJ[t] = __expf(-v); }

    float kl = 0.f;
    for (int i = t; i < Ocnt * MM; i += 256) {
        int ol = i / MM, n = i % MM;
        int gi = (f * Otot + oB + ol) * MM + n;
        float mu = mw[gi];
        float s  = log1pf(__expf(rw[gi]));
        sW[i] = mu + s * ew[gi];
        kl += kl_term(mu, s);
    }
    red[t] = kl;
    __syncthreads();

    // Phase B: one V entry per thread (63-FMA chain).
    for (int i = t; i < Ocnt * MM; i += 256) {
        int ol = i / MM, m = i % MM;
        const float* r = &sR[m * MM];
        const float* w = &sW[ol * MM];
        float v = 0.f;
        #pragma unroll
        for (int n = 0; n < MM; n++) v = fmaf(r[n], w[n], v);
        sP[ol * 64 + (m + 1)] = v * sEU[m];
        sQ[ol * 64 + (m + 1)] = v * sEMU[m];
    }
    if (t < Ocnt) { sP[t * 64] = 0.f; sQ[t * 64] = 0.f; }
    __syncthreads();

    for (int s = 128; s > 0; s >>= 1) {
        if (t < s) red[t] += red[t + s];
        __syncthreads();
    }
    if (t == 0) g_klpart[blk] = red[0];

    // Phase C: one (ol,j) entry per thread.
    for (int e = t; e < Ocnt * 64; e += 256) {
        int ol = e >> 6, j = e & 63;
        const float* p = &sP[ol * 64];
        const float* q = &sQ[ol * 64];
        float A = 0.f, B = 0.f;
        #pragma unroll
        for (int i = 1; i <= 63; i++) {
            A += (i <= j) ? p[i] : 0.f;
            B += (i >  j) ? q[i] : 0.f;
        }
        if (stage == 1) {
            float At = A * sEMJ[j];
            float Bt = B * sEJ[j];
            g_T1[(f * 64 + j) * 16 + (oB + ol)] = make_float2(At + Bt, Bt - At);
        } else if (stage == 2) {
            g_T2[(f * 64 + j) * 16 + (oB + ol)] = make_float2(A, B);
        } else {
            g_T3[j * 16 + f] = make_float2(A, B);
        }
    }
}

// ---------------------------------------------------------------------------
// Forward: half-warp per sample, lane = output channel, float2 broadcast
// slots with embedded j.
// ---------------------------------------------------------------------------
__global__ void __launch_bounds__(256) fwd_kernel(
    const float* __restrict__ x, float* __restrict__ out, int nB, int klIdx)
{
    __shared__ float2 sT[8][64];   // [warp][sub*32 + f]

    // KL: warp-parallel deterministic sum of the NBLK partials.
    if (blockIdx.x == 0 && threadIdx.x < 32) {
        int l = threadIdx.x;
        float s = 0.f;
        for (int i = l; i < NBLK; i += 32) s += g_klpart[i];
        #pragma unroll
        for (int d = 16; d > 0; d >>= 1)
            s += __shfl_xor_sync(0xFFFFFFFFu, s, d);
        if (l == 0) out[klIdx] = s;
    }

    const int warp = threadIdx.x >> 5, lane = threadIdx.x & 31;
    const int sub = lane >> 4, o = lane & 15;
    const int b = blockIdx.x * 16 + warp * 2 + sub;
    const int bc = (b < nB) ? b : (nB - 1);
    const unsigned mask = 0xFFFFu << (sub << 4);

    float2* tw = &sT[warp][sub * 32];

    const float xv0 = __ldg(&x[bc * 32 + o]);
    const float xv1 = __ldg(&x[bc * 32 + 16 + o]);
    const float bs1 = __ldg(&g_bsum1[o]);
    const float bs2 = __ldg(&g_bsum2[o]);
    const float bs3 = __ldg(&g_bsum3);

    // ---- stage 1 precompute: (cosh t [low bits = j], sinh t) ----
    {
        float j0f = fminf(fmaxf(xv0 * 64.f, 0.f), 63.f);
        int   j0  = (int)j0f;
        float t0  = fmaf((float)j0, -0.015625f, xv0);
        float t02 = t0 * t0;
        tw[o] = make_float2(embed_j(fmaf(t02, 0.5f, 1.f), j0),
                            t0 * fmaf(t02, 0.16666667f, 1.f));
        float j1f = fminf(fmaxf(xv1 * 64.f, 0.f), 63.f);
        int   j1  = (int)j1f;
        float t1  = fmaf((float)j1, -0.015625f, xv1);
        float t12 = t1 * t1;
        tw[16 + o] = make_float2(embed_j(fmaf(t12, 0.5f, 1.f), j1),
                                 t1 * fmaf(t12, 0.16666667f, 1.f));
    }
    __syncwarp();

    const char* base1 = (const char*)g_T1 + o * 8;
    float acc = 0.f;
    #pragma unroll
    for (int f = 0; f < 32; f++) {
        float2 tr = tw[f];
        unsigned jb = (__float_as_uint(tr.x) & 63u) << 7;   // j*128
        const float2 pq = *(const float2*)(base1 + f * 8192 + jb);
        acc = fmaf(pq.x, tr.x, fmaf(pq.y, tr.y, acc));
    }
    float h1 = acc + bs1;
    __syncwarp();

    // ---- stage 2 precompute: (e^{-h} [low bits = j], e^{h}) ----
    {
        float ex  = __expf(h1);
        float emx = __expf(-h1);
        int j = (int)fminf(fmaxf(h1 * 64.f, 0.f), 63.f);
        tw[o] = make_float2(embed_j(emx, j), ex);
    }
    __syncwarp();

    const char* base2 = (const char*)g_T2 + o * 8;
    acc = 0.f;
    #pragma unroll
    for (int f = 0; f < 16; f++) {
        float2 tr = tw[f];
        unsigned jb = (__float_as_uint(tr.x) & 63u) << 7;
        const float2 ab = *(const float2*)(base2 + f * 8192 + jb);
        acc = fmaf(tr.x, ab.x, fmaf(tr.y, ab.y, acc));
    }
    float h2 = acc + bs2;

    // ---- stage 3: 16 -> 1 (lane o is feature o) ----
    {
        float ex  = __expf(h2);
        float emx = __expf(-h2);
        int j = (int)fminf(fmaxf(h2 * 64.f, 0.f), 63.f);
        float2 tv = __ldg(&g_T3[j * 16 + o]);
        float c = fmaf(emx, tv.x, ex * tv.y);
        c += __shfl_xor_sync(mask, c, 8);
        c += __shfl_xor_sync(mask, c, 4);
        c += __shfl_xor_sync(mask, c, 2);
        c += __shfl_xor_sync(mask, c, 1);
        if (o == 0 && b < nB) out[b] = c + bs3;
    }
}

// ---------------------------------------------------------------------------
extern "C" void kernel_launch(void* const* d_in, const int* in_sizes, int n_in,
                              void* d_out, int out_size)
{
    const float* x    = (const float*)d_in[0];
    const float* U    = (const float*)d_in[1];
    const float* Rinv = (const float*)d_in[2];

    const float* mw1 = (const float*)d_in[3];
    const float* rw1 = (const float*)d_in[4];
    const float* mb1 = (const float*)d_in[5];
    const float* rb1 = (const float*)d_in[6];
    const float* ew1 = (const float*)d_in[7];
    const float* eb1 = (const float*)d_in[8];

    const float* mw2 = (const float*)d_in[9];
    const float* rw2 = (const float*)d_in[10];
    const float* mb2 = (const float*)d_in[11];
    const float* rb2 = (const float*)d_in[12];
    const float* ew2 = (const float*)d_in[13];
    const float* eb2 = (const float*)d_in[14];

    const float* mw3 = (const float*)d_in[15];
    const float* rw3 = (const float*)d_in[16];
    const float* mb3 = (const float*)d_in[17];
    const float* rb3 = (const float*)d_in[18];
    const float* ew3 = (const float*)d_in[19];
    const float* eb3 = (const float*)d_in[20];

    const int nB = in_sizes[0] / 32;
    float* out = (float*)d_out;

    build_tables<<<NBLK, 256>>>(U, Rinv,
                                mw1, rw1, ew1, mw2, rw2, ew2, mw3, rw3, ew3,
                                mb1, rb1, eb1, mb2, rb2, eb2, mb3, rb3, eb3);
    fwd_kernel<<<(nB + 15) / 16, 256>>>(x, out, nB, out_size - 1);
}

// round 11
// speedup vs baseline: 1.3068x; 1.0203x over previous
#include <cuda_runtime.h>
#include <cuda_bf16.h>

// AdditiveDTMGP: 3-stage additive deep GP, Laplace kernel on dyadic design
// u_i = i/64 (i=1..63), whitened by Rinv (upper-triangular), reparam weights.
//
// Exact split: exp(-|x-u|) = e^{-x}e^{u} (u<=x) / e^{x}e^{-u} (u>x) collapses
// each 63-term sum to a 2-term table lookup at j = floor(64x). Stage 1 tables
// premultiplied by e^{-+j/64}, stored (P,Q) fp32: contribution =
// P*cosh t + Q*sinh t, t in [0,1/64). Stages 2/3 exact (A,B) + exp.
//
// build: 209 blocks (stages 1/2 split 4-ways by output channel).
// fwd: half-warp per sample, lane = output channel; float2 broadcast slots
// with 6-bit j embedded in low mantissa bits of the first component.
// PDL: fwd is launched with programmatic stream serialization; its x-load +
// stage-1 precompute run BEFORE cudaGridDependencySynchronize(), overlapping
// build's tail and the launch gap. Table/bsum/klpart reads come after.

#define MM 63
#define NBLK 209   // 128 stage1 + 64 stage2 + 16 stage3 + 1 bias

__device__ float2 g_T1[32 * 64 * 16];   // stage1 [f][j][o] : (P, Q)
__device__ float2 g_T2[16 * 64 * 16];   // stage2 [f][j][o] : (A, B)
__device__ float2 g_T3[64 * 16];        // stage3 [j][f]    : (A, B)
__device__ float  g_bsum1[16];
__device__ float  g_bsum2[16];
__device__ float  g_bsum3;
__device__ float  g_klpart[NBLK];

__device__ __forceinline__ float kl_term(float mu, float s) {
    return fmaf(0.5f, fmaf(s, s, mu * mu), -__logf(s)) - 0.5f;
}

// Embed 6-bit j into low mantissa bits of v (rounded): <= ~63-ulp perturbation.
__device__ __forceinline__ float embed_j(float v, int j) {
    unsigned b = (__float_as_uint(v) + 32u) & ~63u;
    return __uint_as_float(b | (unsigned)j);
}

// ---------------------------------------------------------------------------
// Prep: 209 blocks.
// ---------------------------------------------------------------------------
__global__ void __launch_bounds__(256) build_tables(
    const float* __restrict__ U, const float* __restrict__ Rinv,
    const float* __restrict__ mw1, const float* __restrict__ rw1, const float* __restrict__ ew1,
    const float* __restrict__ mw2, const float* __restrict__ rw2, const float* __restrict__ ew2,
    const float* __restrict__ mw3, const float* __restrict__ rw3, const float* __restrict__ ew3,
    const float* __restrict__ mb1, const float* __restrict__ rb1, const float* __restrict__ eb1,
    const float* __restrict__ mb2, const float* __restrict__ rb2, const float* __restrict__ eb2,
    const float* __restrict__ mb3, const float* __restrict__ rb3, const float* __restrict__ eb3)
{
    const int blk = blockIdx.x, t = threadIdx.x;
    __shared__ float red[256];

    if (blk == 208) {
        float kl = 0.f;
        for (int i = t; i < 32 * 16; i += 256) kl += kl_term(mb1[i], log1pf(__expf(rb1[i])));
        for (int i = t; i < 16 * 16; i += 256) kl += kl_term(mb2[i], log1pf(__expf(rb2[i])));
        for (int i = t; i < 16;      i += 256) kl += kl_term(mb3[i], log1pf(__expf(rb3[i])));
        if (t < 16) {
            float s = 0.f;
            for (int f = 0; f < 32; f++) {
                int i = f * 16 + t;
                s += mb1[i] + log1pf(__expf(rb1[i])) * eb1[i];
            }
            g_bsum1[t] = s;
        } else if (t < 32) {
            int o = t - 16;
            float s = 0.f;
            for (int f = 0; f < 16; f++) {
                int i = f * 16 + o;
                s += mb2[i] + log1pf(__expf(rb2[i])) * eb2[i];
            }
            g_bsum2[o] = s;
        } else if (t == 32) {
            float s = 0.f;
            for (int f = 0; f < 16; f++)
                s += mb3[f] + log1pf(__expf(rb3[f])) * eb3[f];
            g_bsum3 = s;
        }
        red[t] = kl;
        __syncthreads();
        for (int s = 128; s > 0; s >>= 1) {
            if (t < s) red[t] += red[t + s];
            __syncthreads();
        }
        if (t == 0) g_klpart[208] = red[0];
        cudaTriggerProgrammaticLaunchCompletion();
        return;
    }

    __shared__ float sR[MM * MM];
    __shared__ float sW[4 * MM];
    __shared__ float sP[4 * 64];   // P[ol][i] = e^{i/64} V[ol][i-1], i=1..63
    __shared__ float sQ[4 * 64];
    __shared__ float sEU[MM], sEMU[MM];
    __shared__ float sEJ[64], sEMJ[64];

    int stage, f, oB, Ocnt, Otot;
    const float *mw, *rw, *ew;
    if (blk < 128) {
        stage = 1; f = blk >> 2; oB = (blk & 3) * 4; Ocnt = 4; Otot = 16;
        mw = mw1; rw = rw1; ew = ew1;
    } else if (blk < 192) {
        int bb = blk - 128;
        stage = 2; f = bb >> 2; oB = (bb & 3) * 4; Ocnt = 4; Otot = 16;
        mw = mw2; rw = rw2; ew = ew2;
    } else {
        stage = 3; f = blk - 192; oB = 0; Ocnt = 1; Otot = 1;
        mw = mw3; rw = rw3; ew = ew3;
    }

    #pragma unroll 4
    for (int i = t; i < MM * MM; i += 256) sR[i] = Rinv[i];
    if (t < MM) { float u = U[t]; sEU[t] = __expf(u); sEMU[t] = __expf(-u); }
    if (t < 64) { float v = (float)t * 0.015625f; sEJ[t] = __expf(v); sEMJ[t] = __expf(-v); }

    float kl = 0.f;
    for (int i = t; i < Ocnt * MM; i += 256) {
        int ol = i / MM, n = i % MM;
        int gi = (f * Otot + oB + ol) * MM + n;
        float mu = mw[gi];
        float s  = log1pf(__expf(rw[gi]));
        sW[i] = mu + s * ew[gi];
        kl += kl_term(mu, s);
    }
    red[t] = kl;
    __syncthreads();

    // Phase B: one V entry per thread (63-FMA chain).
    for (int i = t; i < Ocnt * MM; i += 256) {
        int ol = i / MM, m = i % MM;
        const float* r = &sR[m * MM];
        const float* w = &sW[ol * MM];
        float v = 0.f;
        #pragma unroll
        for (int n = 0; n < MM; n++) v = fmaf(r[n], w[n], v);
        sP[ol * 64 + (m + 1)] = v * sEU[m];
        sQ[ol * 64 + (m + 1)] = v * sEMU[m];
    }
    if (t < Ocnt) { sP[t * 64] = 0.f; sQ[t * 64] = 0.f; }
    __syncthreads();

    for (int s = 128; s > 0; s >>= 1) {
        if (t < s) red[t] += red[t + s];
        __syncthreads();
    }
    if (t == 0) g_klpart[blk] = red[0];

    // Phase C: one (ol,j) entry per thread.
    for (int e = t; e < Ocnt * 64; e += 256) {
        int ol = e >> 6, j = e & 63;
        const float* p = &sP[ol * 64];
        const float* q = &sQ[ol * 64];
        float A = 0.f, B = 0.f;
        #pragma unroll
        for (int i = 1; i <= 63; i++) {
            A += (i <= j) ? p[i] : 0.f;
            B += (i >  j) ? q[i] : 0.f;
        }
        if (stage == 1) {
            float At = A * sEMJ[j];
            float Bt = B * sEJ[j];
            g_T1[(f * 64 + j) * 16 + (oB + ol)] = make_float2(At + Bt, Bt - At);
        } else if (stage == 2) {
            g_T2[(f * 64 + j) * 16 + (oB + ol)] = make_float2(A, B);
        } else {
            g_T3[j * 16 + f] = make_float2(A, B);
        }
    }
    cudaTriggerProgrammaticLaunchCompletion();
}

// ---------------------------------------------------------------------------
// Forward. Prologue (x load + stage-1 precompute) runs BEFORE the PDL
// dependency sync; all table/bsum/klpart reads come after.
// ---------------------------------------------------------------------------
__global__ void __launch_bounds__(256) fwd_kernel(
    const float* __restrict__ x, float* __restrict__ out, int nB, int klIdx)
{
    __shared__ float2 sT[8][64];   // [warp][sub*32 + f]

    const int warp = threadIdx.x >> 5, lane = threadIdx.x & 31;
    const int sub = lane >> 4, o = lane & 15;
    const int b = blockIdx.x * 16 + warp * 2 + sub;
    const int bc = (b < nB) ? b : (nB - 1);
    const unsigned mask = 0xFFFFu << (sub << 4);

    float2* tw = &sT[warp][sub * 32];

    // ---- pre-sync: x loads + stage-1 precompute (independent of build) ----
    const float xv0 = __ldg(&x[bc * 32 + o]);
    const float xv1 = __ldg(&x[bc * 32 + 16 + o]);
    {
        float j0f = fminf(fmaxf(xv0 * 64.f, 0.f), 63.f);
        int   j0  = (int)j0f;
        float t0  = fmaf((float)j0, -0.015625f, xv0);
        float t02 = t0 * t0;
        tw[o] = make_float2(embed_j(fmaf(t02, 0.5f, 1.f), j0),
                            t0 * fmaf(t02, 0.16666667f, 1.f));
        float j1f = fminf(fmaxf(xv1 * 64.f, 0.f), 63.f);
        int   j1  = (int)j1f;
        float t1  = fmaf((float)j1, -0.015625f, xv1);
        float t12 = t1 * t1;
        tw[16 + o] = make_float2(embed_j(fmaf(t12, 0.5f, 1.f), j1),
                                 t1 * fmaf(t12, 0.16666667f, 1.f));
    }
    __syncwarp();

    // ---- wait for build_tables results to be visible ----
    cudaGridDependencySynchronize();

    // KL: warp-parallel deterministic sum of the NBLK partials.
    if (blockIdx.x == 0 && threadIdx.x < 32) {
        int l = threadIdx.x;
        float s = 0.f;
        for (int i = l; i < NBLK; i += 32) s += g_klpart[i];
        #pragma unroll
        for (int d = 16; d > 0; d >>= 1)
            s += __shfl_xor_sync(0xFFFFFFFFu, s, d);
        if (l == 0) out[klIdx] = s;
    }

    const float bs1 = __ldg(&g_bsum1[o]);
    const float bs2 = __ldg(&g_bsum2[o]);
    const float bs3 = __ldg(&g_bsum3);

    const char* base1 = (const char*)g_T1 + o * 8;
    float acc = 0.f;
    #pragma unroll
    for (int f = 0; f < 32; f++) {
        float2 tr = tw[f];
        unsigned jb = (__float_as_uint(tr.x) & 63u) << 7;   // j*128
        const float2 pq = *(const float2*)(base1 + f * 8192 + jb);
        acc = fmaf(pq.x, tr.x, fmaf(pq.y, tr.y, acc));
    }
    float h1 = acc + bs1;
    __syncwarp();

    // ---- stage 2 precompute: (e^{-h} [low bits = j], e^{h}) ----
    {
        float ex  = __expf(h1);
        float emx = __expf(-h1);
        int j = (int)fminf(fmaxf(h1 * 64.f, 0.f), 63.f);
        tw[o] = make_float2(embed_j(emx, j), ex);
    }
    __syncwarp();

    const char* base2 = (const char*)g_T2 + o * 8;
    acc = 0.f;
    #pragma unroll
    for (int f = 0; f < 16; f++) {
        float2 tr = tw[f];
        unsigned jb = (__float_as_uint(tr.x) & 63u) << 7;
        const float2 ab = *(const float2*)(base2 + f * 8192 + jb);
        acc = fmaf(tr.x, ab.x, fmaf(tr.y, ab.y, acc));
    }
    float h2 = acc + bs2;

    // ---- stage 3: 16 -> 1 (lane o is feature o) ----
    {
        float ex  = __expf(h2);
        float emx = __expf(-h2);
        int j = (int)fminf(fmaxf(h2 * 64.f, 0.f), 63.f);
        float2 tv = __ldg(&g_T3[j * 16 + o]);
        float c = fmaf(emx, tv.x, ex * tv.y);
        c += __shfl_xor_sync(mask, c, 8);
        c += __shfl_xor_sync(mask, c, 4);
        c += __shfl_xor_sync(mask, c, 2);
        c += __shfl_xor_sync(mask, c, 1);
        if (o == 0 && b < nB) out[b] = c + bs3;
    }
}

// ---------------------------------------------------------------------------
extern "C" void kernel_launch(void* const* d_in, const int* in_sizes, int n_in,
                              void* d_out, int out_size)
{
    const float* x    = (const float*)d_in[0];
    const float* U    = (const float*)d_in[1];
    const float* Rinv = (const float*)d_in[2];

    const float* mw1 = (const float*)d_in[3];
    const float* rw1 = (const float*)d_in[4];
    const float* mb1 = (const float*)d_in[5];
    const float* rb1 = (const float*)d_in[6];
    const float* ew1 = (const float*)d_in[7];
    const float* eb1 = (const float*)d_in[8];

    const float* mw2 = (const float*)d_in[9];
    const float* rw2 = (const float*)d_in[10];
    const float* mb2 = (const float*)d_in[11];
    const float* rb2 = (const float*)d_in[12];
    const float* ew2 = (const float*)d_in[13];
    const float* eb2 = (const float*)d_in[14];

    const float* mw3 = (const float*)d_in[15];
    const float* rw3 = (const float*)d_in[16];
    const float* mb3 = (const float*)d_in[17];
    const float* rb3 = (const float*)d_in[18];
    const float* ew3 = (const float*)d_in[19];
    const float* eb3 = (const float*)d_in[20];

    const int nB = in_sizes[0] / 32;
    float* out = (float*)d_out;

    build_tables<<<NBLK, 256>>>(U, Rinv,
                                mw1, rw1, ew1, mw2, rw2, ew2, mw3, rw3, ew3,
                                mb1, rb1, eb1, mb2, rb2, eb2, mb3, rb3, eb3);

    // fwd with programmatic dependent launch: starts while build drains;
    // pre-sync section only touches x.
    cudaLaunchConfig_t cfg = {};
    cfg.gridDim  = dim3((unsigned)((nB + 15) / 16));
    cfg.blockDim = dim3(256);
    cudaLaunchAttribute attrs[1];
    attrs[0].id = cudaLaunchAttributeProgrammaticStreamSerialization;
    attrs[0].val.programmaticStreamSerializationAllowed = 1;
    cfg.attrs = attrs;
    cfg.numAttrs = 1;
    cudaLaunchKernelEx(&cfg, fwd_kernel, x, out, nB, out_size - 1);
}

// round 12
// speedup vs baseline: 1.3362x; 1.0225x over previous
#include <cuda_runtime.h>
#include <cuda_bf16.h>

// AdditiveDTMGP: 3-stage additive deep GP, Laplace kernel on dyadic design
// u_i = i/64 (i=1..63), whitened by Rinv (upper-triangular), reparam weights.
//
// Exact split: exp(-|x-u|) = e^{-x}e^{u} (u<=x) / e^{x}e^{-u} (u>x) collapses
// each 63-term sum to a 2-term table lookup at j = floor(64x). Stage 1 tables
// premultiplied by e^{-+j/64}, stored (P,Q) fp32. Stages 2/3 exact (A,B)+exp.
//
// build: 209 blocks; Phase C uses a segmented warp scan (prefix P, prefix Q,
// B = Qtot - prefixQ) instead of a 63-iter predicated loop.
// fwd: half-warp per sample, lane = output channel; float2 broadcast slots
// with 6-bit j embedded in low mantissa bits; PDL overlaps build's tail.

#define MM 63
#define NBLK 209   // 128 stage1 + 64 stage2 + 16 stage3 + 1 bias

__device__ float2 g_T1[32 * 64 * 16];   // stage1 [f][j][o] : (P, Q)
__device__ float2 g_T2[16 * 64 * 16];   // stage2 [f][j][o] : (A, B)
__device__ float2 g_T3[64 * 16];        // stage3 [j][f]    : (A, B)
__device__ float  g_bsum1[16];
__device__ float  g_bsum2[16];
__device__ float  g_bsum3;
__device__ float  g_klpart[NBLK];

__device__ __forceinline__ float kl_term(float mu, float s) {
    return fmaf(0.5f, fmaf(s, s, mu * mu), -__logf(s)) - 0.5f;
}

// Embed 6-bit j into low mantissa bits of v (rounded): <= ~63-ulp perturbation.
__device__ __forceinline__ float embed_j(float v, int j) {
    unsigned b = (__float_as_uint(v) + 32u) & ~63u;
    return __uint_as_float(b | (unsigned)j);
}

// ---------------------------------------------------------------------------
// Prep: 209 blocks.
//   [0,128)   stage1: f = blk>>2, o-range [(blk&3)*4, +4)
//   [128,192) stage2: f = (blk-128)>>2, o-range [(blk&3)*4, +4)
//   [192,208) stage3: f = blk-192, O=1
//   208       bias sums + bias-KL
// ---------------------------------------------------------------------------
__global__ void __launch_bounds__(256) build_tables(
    const float* __restrict__ U, const float* __restrict__ Rinv,
    const float* __restrict__ mw1, const float* __restrict__ rw1, const float* __restrict__ ew1,
    const float* __restrict__ mw2, const float* __restrict__ rw2, const float* __restrict__ ew2,
    const float* __restrict__ mw3, const float* __restrict__ rw3, const float* __restrict__ ew3,
    const float* __restrict__ mb1, const float* __restrict__ rb1, const float* __restrict__ eb1,
    const float* __restrict__ mb2, const float* __restrict__ rb2, const float* __restrict__ eb2,
    const float* __restrict__ mb3, const float* __restrict__ rb3, const float* __restrict__ eb3)
{
    const int blk = blockIdx.x, t = threadIdx.x;
    __shared__ float red[256];

    if (blk == 208) {
        float kl = 0.f;
        for (int i = t; i < 32 * 16; i += 256) kl += kl_term(mb1[i], log1pf(__expf(rb1[i])));
        for (int i = t; i < 16 * 16; i += 256) kl += kl_term(mb2[i], log1pf(__expf(rb2[i])));
        for (int i = t; i < 16;      i += 256) kl += kl_term(mb3[i], log1pf(__expf(rb3[i])));
        if (t < 16) {
            float s = 0.f;
            for (int f = 0; f < 32; f++) {
                int i = f * 16 + t;
                s += mb1[i] + log1pf(__expf(rb1[i])) * eb1[i];
            }
            g_bsum1[t] = s;
        } else if (t < 32) {
            int o = t - 16;
            float s = 0.f;
            for (int f = 0; f < 16; f++) {
                int i = f * 16 + o;
                s += mb2[i] + log1pf(__expf(rb2[i])) * eb2[i];
            }
            g_bsum2[o] = s;
        } else if (t == 32) {
            float s = 0.f;
            for (int f = 0; f < 16; f++)
                s += mb3[f] + log1pf(__expf(rb3[f])) * eb3[f];
            g_bsum3 = s;
        }
        red[t] = kl;
        __syncthreads();
        for (int s = 128; s > 0; s >>= 1) {
            if (t < s) red[t] += red[t + s];
            __syncthreads();
        }
        if (t == 0) g_klpart[208] = red[0];
        cudaTriggerProgrammaticLaunchCompletion();
        return;
    }

    __shared__ float sR[MM * MM + 1];
    __shared__ float sW[4 * MM];
    __shared__ float sP[4 * 64];   // P[ol][i] = e^{i/64} V[ol][i-1], i=1..63
    __shared__ float sQ[4 * 64];
    __shared__ float sEU[MM], sEMU[MM];
    __shared__ float sEJ[64], sEMJ[64];
    __shared__ float wtP[8], wtQ[8];

    int stage, f, oB, Ocnt, Otot;
    const float *mw, *rw, *ew;
    if (blk < 128) {
        stage = 1; f = blk >> 2; oB = (blk & 3) * 4; Ocnt = 4; Otot = 16;
        mw = mw1; rw = rw1; ew = ew1;
    } else if (blk < 192) {
        int bb = blk - 128;
        stage = 2; f = bb >> 2; oB = (bb & 3) * 4; Ocnt = 4; Otot = 16;
        mw = mw2; rw = rw2; ew = ew2;
    } else {
        stage = 3; f = blk - 192; oB = 0; Ocnt = 1; Otot = 1;
        mw = mw3; rw = rw3; ew = ew3;
    }

    // Rinv staging with float4 loads (3969 = 992*4 + 1).
    {
        const float4* R4 = (const float4*)Rinv;
        float4* S4 = (float4*)sR;
        #pragma unroll 4
        for (int i = t; i < 992; i += 256) S4[i] = R4[i];
        if (t == 0) sR[3968] = Rinv[3968];
    }
    if (t < MM) { float u = U[t]; sEU[t] = __expf(u); sEMU[t] = __expf(-u); }
    if (t < 64) { float v = (float)t * 0.015625f; sEJ[t] = __expf(v); sEMJ[t] = __expf(-v); }
    // Zero sP/sQ so inactive segments (stage 3) scan clean values.
    sP[t] = 0.f; sQ[t] = 0.f;

    // Phase A: effective weights + weight-KL partial.
    float kl = 0.f;
    for (int i = t; i < Ocnt * MM; i += 256) {
        int ol = i / MM, n = i % MM;
        int gi = (f * Otot + oB + ol) * MM + n;
        float mu = mw[gi];
        float s  = log1pf(__expf(rw[gi]));
        sW[i] = mu + s * ew[gi];
        kl += kl_term(mu, s);
    }
    red[t] = kl;
    __syncthreads();

    // Phase B: one V entry per thread (63-FMA chain).
    for (int i = t; i < Ocnt * MM; i += 256) {
        int ol = i / MM, m = i % MM;
        const float* r = &sR[m * MM];
        const float* w = &sW[ol * MM];
        float v = 0.f;
        #pragma unroll
        for (int n = 0; n < MM; n++) v = fmaf(r[n], w[n], v);
        sP[ol * 64 + (m + 1)] = v * sEU[m];
        sQ[ol * 64 + (m + 1)] = v * sEMU[m];
    }
    __syncthreads();

    // Phase C: segmented scan over i (segments of 64 = 2 warps each).
    // A[j] = inclusive-prefix P at j; B[j] = Qtot - inclusive-prefix Q at j.
    {
        const int lane = t & 31, wid = t >> 5;
        float p = sP[t], q = sQ[t];
        #pragma unroll
        for (int d = 1; d < 32; d <<= 1) {
            float np = __shfl_up_sync(0xFFFFFFFFu, p, d);
            float nq = __shfl_up_sync(0xFFFFFFFFu, q, d);
            if (lane >= d) { p += np; q += nq; }
        }
        if (lane == 31) { wtP[wid] = p; wtQ[wid] = q; }
        __syncthreads();
        if (wid & 1) { p += wtP[wid - 1]; q += wtQ[wid - 1]; }
        int seg = t >> 6;                       // = ol
        float qtot = wtQ[seg * 2] + wtQ[seg * 2 + 1];
        float A = p;
        float B = qtot - q;

        if (t < Ocnt * 64) {
            int ol = seg, j = t & 63;
            if (stage == 1) {
                float At = A * sEMJ[j];
                float Bt = B * sEJ[j];
                g_T1[(f * 64 + j) * 16 + (oB + ol)] = make_float2(At + Bt, Bt - At);
            } else if (stage == 2) {
                g_T2[(f * 64 + j) * 16 + (oB + ol)] = make_float2(A, B);
            } else {
                g_T3[j * 16 + f] = make_float2(A, B);
            }
        }
    }

    // KL partial reduction.
    __syncthreads();
    for (int s = 128; s > 0; s >>= 1) {
        if (t < s) red[t] += red[t + s];
        __syncthreads();
    }
    if (t == 0) g_klpart[blk] = red[0];
    cudaTriggerProgrammaticLaunchCompletion();
}

// ---------------------------------------------------------------------------
// Forward. Prologue (x load + stage-1 precompute) runs BEFORE the PDL
// dependency sync; all table/bsum/klpart reads come after.
// ---------------------------------------------------------------------------
__global__ void __launch_bounds__(256) fwd_kernel(
    const float* __restrict__ x, float* __restrict__ out, int nB, int klIdx)
{
    __shared__ float2 sT[8][64];   // [warp][sub*32 + f]

    const int warp = threadIdx.x >> 5, lane = threadIdx.x & 31;
    const int sub = lane >> 4, o = lane & 15;
    const int b = blockIdx.x * 16 + warp * 2 + sub;
    const int bc = (b < nB) ? b : (nB - 1);
    const unsigned mask = 0xFFFFu << (sub << 4);

    float2* tw = &sT[warp][sub * 32];

    // ---- pre-sync: x loads + stage-1 precompute (independent of build) ----
    const float xv0 = __ldg(&x[bc * 32 + o]);
    const float xv1 = __ldg(&x[bc * 32 + 16 + o]);
    {
        float j0f = fminf(fmaxf(xv0 * 64.f, 0.f), 63.f);
        int   j0  = (int)j0f;
        float t0  = fmaf((float)j0, -0.015625f, xv0);
        float t02 = t0 * t0;
        tw[o] = make_float2(embed_j(fmaf(t02, 0.5f, 1.f), j0),
                            t0 * fmaf(t02, 0.16666667f, 1.f));
        float j1f = fminf(fmaxf(xv1 * 64.f, 0.f), 63.f);
        int   j1  = (int)j1f;
        float t1  = fmaf((float)j1, -0.015625f, xv1);
        float t12 = t1 * t1;
        tw[16 + o] = make_float2(embed_j(fmaf(t12, 0.5f, 1.f), j1),
                                 t1 * fmaf(t12, 0.16666667f, 1.f));
    }
    __syncwarp();

    // ---- wait for build_tables results to be visible ----
    cudaGridDependencySynchronize();

    // KL: warp-parallel deterministic sum of the NBLK partials.
    if (blockIdx.x == 0 && threadIdx.x < 32) {
        int l = threadIdx.x;
        float s = 0.f;
        for (int i = l; i < NBLK; i += 32) s += g_klpart[i];
        #pragma unroll
        for (int d = 16; d > 0; d >>= 1)
            s += __shfl_xor_sync(0xFFFFFFFFu, s, d);
        if (l == 0) out[klIdx] = s;
    }

    const float bs1 = __ldg(&g_bsum1[o]);
    const float bs2 = __ldg(&g_bsum2[o]);
    const float bs3 = __ldg(&g_bsum3);

    const char* base1 = (const char*)g_T1 + o * 8;
    float acc = 0.f;
    #pragma unroll
    for (int f = 0; f < 32; f++) {
        float2 tr = tw[f];
        unsigned jb = (__float_as_uint(tr.x) & 63u) << 7;   // j*128
        const float2 pq = *(const float2*)(base1 + f * 8192 + jb);
        acc = fmaf(pq.x, tr.x, fmaf(pq.y, tr.y, acc));
    }
    float h1 = acc + bs1;
    __syncwarp();

    // ---- stage 2 precompute: (e^{-h} [low bits = j], e^{h}) ----
    {
        float ex  = __expf(h1);
        float emx = __expf(-h1);
        int j = (int)fminf(fmaxf(h1 * 64.f, 0.f), 63.f);
        tw[o] = make_float2(embed_j(emx, j), ex);
    }
    __syncwarp();

    const char* base2 = (const char*)g_T2 + o * 8;
    acc = 0.f;
    #pragma unroll
    for (int f = 0; f < 16; f++) {
        float2 tr = tw[f];
        unsigned jb = (__float_as_uint(tr.x) & 63u) << 7;
        const float2 ab = *(const float2*)(base2 + f * 8192 + jb);
        acc = fmaf(tr.x, ab.x, fmaf(tr.y, ab.y, acc));
    }
    float h2 = acc + bs2;

    // ---- stage 3: 16 -> 1 (lane o is feature o) ----
    {
        float ex  = __expf(h2);
        float emx = __expf(-h2);
        int j = (int)fminf(fmaxf(h2 * 64.f, 0.f), 63.f);
        float2 tv = __ldg(&g_T3[j * 16 + o]);
        float c = fmaf(emx, tv.x, ex * tv.y);
        c += __shfl_xor_sync(mask, c, 8);
        c += __shfl_xor_sync(mask, c, 4);
        c += __shfl_xor_sync(mask, c, 2);
        c += __shfl_xor_sync(mask, c, 1);
        if (o == 0 && b < nB) out[b] = c + bs3;
    }
}

// ---------------------------------------------------------------------------
extern "C" void kernel_launch(void* const* d_in, const int* in_sizes, int n_in,
                              void* d_out, int out_size)
{
    const float* x    = (const float*)d_in[0];
    const float* U    = (const float*)d_in[1];
    const float* Rinv = (const float*)d_in[2];

    const float* mw1 = (const float*)d_in[3];
    const float* rw1 = (const float*)d_in[4];
    const float* mb1 = (const float*)d_in[5];
    const float* rb1 = (const float*)d_in[6];
    const float* ew1 = (const float*)d_in[7];
    const float* eb1 = (const float*)d_in[8];

    const float* mw2 = (const float*)d_in[9];
    const float* rw2 = (const float*)d_in[10];
    const float* mb2 = (const float*)d_in[11];
    const float* rb2 = (const float*)d_in[12];
    const float* ew2 = (const float*)d_in[13];
    const float* eb2 = (const float*)d_in[14];

    const float* mw3 = (const float*)d_in[15];
    const float* rw3 = (const float*)d_in[16];
    const float* mb3 = (const float*)d_in[17];
    const float* rb3 = (const float*)d_in[18];
    const float* ew3 = (const float*)d_in[19];
    const float* eb3 = (const float*)d_in[20];

    const int nB = in_sizes[0] / 32;
    float* out = (float*)d_out;

    build_tables<<<NBLK, 256>>>(U, Rinv,
                                mw1, rw1, ew1, mw2, rw2, ew2, mw3, rw3, ew3,
                                mb1, rb1, eb1, mb2, rb2, eb2, mb3, rb3, eb3);

    // fwd with programmatic dependent launch: starts while build drains;
    // pre-sync section only touches x.
    cudaLaunchConfig_t cfg = {};
    cfg.gridDim  = dim3((unsigned)((nB + 15) / 16));
    cfg.blockDim = dim3(256);
    cudaLaunchAttribute attrs[1];
    attrs[0].id = cudaLaunchAttributeProgrammaticStreamSerialization;
    attrs[0].val.programmaticStreamSerializationAllowed = 1;
    cfg.attrs = attrs;
    cfg.numAttrs = 1;
    cudaLaunchKernelEx(&cfg, fwd_kernel, x, out, nB, out_size - 1);
}